// round 7
// baseline (speedup 1.0000x reference)
#include <cuda_runtime.h>
#include <cuda_bf16.h>

#define HID   64
#define NFLD  2
#define NHH   32
#define NMF   8
#define NTS   4
#define NLAY  9          // hidden (relu,linear) layers in edge MLP
#define MAXN  10016

typedef unsigned long long u64;

// ---------------- scratch (device globals; no allocation allowed) -----------
__device__ float g_Ptop[MAXN * HID];
__device__ float g_Pbot[MAXN * HID];
__device__ float g_acc [MAXN * HID];
__device__ float g_meshh[MAXN * NHH];
__device__ float g_Fprev[MAXN * NFLD];

// ---------------- packed fp32 helpers (FFMA2 path) ---------------------------
__device__ __forceinline__ u64 pack2(float x, float y) {
    u64 r;
    asm("mov.b64 %0, {%1, %2};" : "=l"(r) : "f"(x), "f"(y));
    return r;
}
__device__ __forceinline__ float2 unpack2(u64 v) {
    float2 r;
    asm("mov.b64 {%0, %1}, %2;" : "=f"(r.x), "=f"(r.y) : "l"(v));
    return r;
}
__device__ __forceinline__ void ffma2(u64& d, u64 a, u64 b) {
    asm("fma.rn.f32x2 %0, %1, %2, %0;" : "+l"(d) : "l"(a), "l"(b));
}

// ---------------- per-node projection for mesh-descriptor pass --------------
__global__ void proj_md_kernel(const float* __restrict__ X,
                               const float* __restrict__ W0,
                               float* __restrict__ Ptop, float* __restrict__ Pbot,
                               float* __restrict__ acc, int Nn)
{
    int idx = blockIdx.x * blockDim.x + threadIdx.x;
    if (idx >= Nn * HID) return;
    int n = idx >> 6, j = idx & 63;
    float st = 0.f, sb = 0.f;
#pragma unroll
    for (int k = 0; k < NMF; k++) {
        float x = X[n * NMF + k];
        st = fmaf(x, W0[k * HID + j], st);
        sb = fmaf(x, W0[(NMF + k) * HID + j], sb);
    }
    Ptop[idx] = st;
    Pbot[idx] = sb;
    acc[idx]  = 0.f;
}

// ---------------- fused node encoder + projection (ds pass) ------------------
__global__ void encproj_ds_kernel(const float* __restrict__ meshh,
                                  const float* __restrict__ Fprev,
                                  const float* __restrict__ Fb, int t,
                                  const float* __restrict__ encW,
                                  const float* __restrict__ encb,
                                  const float* __restrict__ W0,
                                  float* __restrict__ Ptop, float* __restrict__ Pbot,
                                  float* __restrict__ acc, int Nn)
{
    __shared__ float sh[4][64];
    int tid = threadIdx.x;
    int q = tid >> 6, j = tid & 63;
    int n = blockIdx.x * 4 + q;
    float s = encb[j];
    if (n < Nn) {
#pragma unroll
        for (int k = 0; k < NHH; k++)
            s = fmaf(meshh[n * NHH + k], encW[k * HID + j], s);
        s = fmaf(Fprev[n * NFLD + 0], encW[(NHH + 0) * HID + j], s);
        s = fmaf(Fprev[n * NFLD + 1], encW[(NHH + 1) * HID + j], s);
        s = fmaf(Fb[n * NTS + t],     encW[(NHH + 2) * HID + j], s);
    }
    sh[q][j] = fmaxf(s, 0.f);
    __syncthreads();
    if (n < Nn) {
        float st = 0.f, sb = 0.f;
#pragma unroll 8
        for (int k = 0; k < HID; k++) {
            float x = sh[q][k];
            st = fmaf(x, W0[k * HID + j], st);
            sb = fmaf(x, W0[(HID + k) * HID + j], sb);
        }
        int idx = n * HID + j;
        Ptop[idx] = st;
        Pbot[idx] = sb;
        acc[idx]  = 0.f;
    }
}

// ---------------- fused edge MLP + scatter -----------------------------------
// Tile: 64 edges x 64 cols, 256 threads. Activations stored DUPLICATED in
// smem: A[k][2e] = A[k][2e+1] = a_e, so the packed FFMA2 A-operand comes
// straight from one LDS.128 (zero MOVs in the k-loop).
// Warp tile 16e x 32c, lane tile 2e x 8c:
//   per warp-k:  1x LDS.128 A (128B, 1 phase) + 2x LDS W (<=64B span, 2 phases)
//                + 8 FFMA2  -> 11 issue slots, 3 crossbar phases.
// One __syncthreads per layer (A and W both ping-ponged; W prefetched to regs
// via LDG during compute, STS'd before the barrier).
// dyn smem: A dup ping/pong 2*64*128 + W ping/pong 2*64*64 floats = 98304 B.
__global__ void __launch_bounds__(256, 2)
edge_mlp_kernel(const float* __restrict__ Ptop, const float* __restrict__ Pbot,
                const float* __restrict__ b0,
                const float* __restrict__ Wh,  // (9,64,64)
                const float* __restrict__ Bh,  // (9,64)
                const int* __restrict__ src, const int* __restrict__ dst,
                float* __restrict__ acc, int E)
{
    extern __shared__ float smem[];
    float* A0  = smem;                 // [64][128]  (64 edges duplicated)
    float* A1  = smem + 64 * 128;      // [64][128]
    float* Ws0 = smem + 2 * 64 * 128;  // [64][64]
    float* Ws1 = Ws0 + 64 * 64;        // [64][64]

    const int tid  = threadIdx.x;
    const int lane = tid & 31, wid = tid >> 5;
    const int eg   = wid & 3;          // edge group (16 edges)
    const int cb   = wid >> 2;         // col block (32 cols)
    const int le   = lane & 7;         // edge-pair within group
    const int lj   = lane >> 3;        // col octet within block
    const int ep   = eg * 8 + le;      // global edge-pair (edges 2ep, 2ep+1)
    const int j0   = cb * 32 + lj * 8; // first of 8 cols
    const int e0   = blockIdx.x * 64;

    // ---- prologue: gather h0 = relu(Ptop[dst]+Pbot[src]+b0), store dup ----
    for (int i = tid; i < 64 * 16; i += 256) {
        int kq = i >> 6;            // float4 group 0..15
        int e  = i & 63;            // edge (consecutive lanes)
        int ge = e0 + e;
        float4 vt = make_float4(0.f, 0.f, 0.f, 0.f);
        float4 vb = make_float4(0.f, 0.f, 0.f, 0.f);
        if (ge < E) {
            int d = dst[ge], s = src[ge];
            vt = *(const float4*)(Ptop + d * HID + kq * 4);
            vb = *(const float4*)(Pbot + s * HID + kq * 4);
        }
        float4 bb = *(const float4*)(b0 + kq * 4);
        int k = kq * 4;
        float v0 = fmaxf(vt.x + vb.x + bb.x, 0.f);
        float v1 = fmaxf(vt.y + vb.y + bb.y, 0.f);
        float v2 = fmaxf(vt.z + vb.z + bb.z, 0.f);
        float v3 = fmaxf(vt.w + vb.w + bb.w, 0.f);
        *(float2*)(A0 + (k + 0) * 128 + 2 * e) = make_float2(v0, v0);
        *(float2*)(A0 + (k + 1) * 128 + 2 * e) = make_float2(v1, v1);
        *(float2*)(A0 + (k + 2) * 128 + 2 * e) = make_float2(v2, v2);
        *(float2*)(A0 + (k + 3) * 128 + 2 * e) = make_float2(v3, v3);
    }

    // stage layer-0 weights into Ws0
    {
        const float4* Wg = (const float4*)Wh;
#pragma unroll
        for (int i = 0; i < 4; i++)
            ((float4*)Ws0)[tid * 4 + i] = Wg[tid * 4 + i];
    }
    __syncthreads();   // A0 + Ws0 ready

    float* Acur = A0;  float* Anxt = A1;
    float* Wcur = Ws0; float* Wnxt = Ws1;

    for (int l = 0; l < NLAY; l++) {
        // prefetch next layer's weights into registers (latency hidden)
        float4 wreg[4];
        if (l + 1 < NLAY) {
            const float4* Wg = (const float4*)(Wh + (l + 1) * HID * HID);
#pragma unroll
            for (int i = 0; i < 4; i++) wreg[i] = Wg[tid * 4 + i];
        }

        // bias init: packed (b_j, b_j+1) col-pairs, replicated over 2 edges
        u64 acc2[2][4];
#pragma unroll
        for (int jp = 0; jp < 4; jp++) {
            float2 b2 = *(const float2*)(Bh + l * HID + j0 + jp * 2);
            u64 bp = pack2(b2.x, b2.y);
            acc2[0][jp] = bp;
            acc2[1][jp] = bp;
        }

#pragma unroll 8
        for (int k = 0; k < HID; k++) {
            ulonglong2 av  = *(const ulonglong2*)(Acur + (k << 7) + (ep << 2));
            ulonglong2 w01 = *(const ulonglong2*)(Wcur + (k << 6) + j0);
            ulonglong2 w23 = *(const ulonglong2*)(Wcur + (k << 6) + j0 + 4);
            u64 wp[4] = {w01.x, w01.y, w23.x, w23.y};
            ffma2(acc2[0][0], av.x, wp[0]);
            ffma2(acc2[0][1], av.x, wp[1]);
            ffma2(acc2[0][2], av.x, wp[2]);
            ffma2(acc2[0][3], av.x, wp[3]);
            ffma2(acc2[1][0], av.y, wp[0]);
            ffma2(acc2[1][1], av.y, wp[1]);
            ffma2(acc2[1][2], av.y, wp[2]);
            ffma2(acc2[1][3], av.y, wp[3]);
        }

        // write next activations duplicated; relu except last layer
        const bool dorelu = (l != NLAY - 1);
#pragma unroll
        for (int jp = 0; jp < 4; jp++) {
            float2 v0 = unpack2(acc2[0][jp]);   // edge 2ep:   cols ja, jb
            float2 v1 = unpack2(acc2[1][jp]);   // edge 2ep+1: cols ja, jb
            if (dorelu) {
                v0.x = fmaxf(v0.x, 0.f); v0.y = fmaxf(v0.y, 0.f);
                v1.x = fmaxf(v1.x, 0.f); v1.y = fmaxf(v1.y, 0.f);
            }
            int ja = j0 + 2 * jp, jb = ja + 1;
            *(float4*)(Anxt + (ja << 7) + (ep << 2)) = make_float4(v0.x, v0.x, v1.x, v1.x);
            *(float4*)(Anxt + (jb << 7) + (ep << 2)) = make_float4(v0.y, v0.y, v1.y, v1.y);
        }

        // stage prefetched weights into the other W buffer
        if (l + 1 < NLAY) {
#pragma unroll
            for (int i = 0; i < 4; i++)
                ((float4*)Wnxt)[tid * 4 + i] = wreg[i];
        }

        __syncthreads();   // single per-layer barrier

        float* t;
        t = Acur; Acur = Anxt; Anxt = t;
        t = Wcur; Wcur = Wnxt; Wnxt = t;
    }

    // ---- epilogue: segment-sum scatter by src ----
    {
        int e  = tid >> 2;            // 0..63
        int qf = (tid & 3) * 16;      // feature quarter
        int ge = e0 + e;
        if (ge < E) {
            int node = src[ge];
            float* ap = acc + node * HID + qf;
#pragma unroll
            for (int kk = 0; kk < 16; kk++)
                atomicAdd(ap + kk, Acur[((qf + kk) << 7) + (e << 1)]);
        }
    }
}

// ---------------- node decoder (mesh descriptor) -----------------------------
__global__ void dec_md_kernel(const float* __restrict__ acc,
                              const float* __restrict__ dw1, const float* __restrict__ db1,
                              const float* __restrict__ dw2, const float* __restrict__ db2,
                              float* __restrict__ meshh, int Nn)
{
    __shared__ float t1[4][64];
    int tid = threadIdx.x;
    int q = tid >> 6, j = tid & 63;
    int n = blockIdx.x * 4 + q;
    float s = db1[j];
    if (n < Nn) {
#pragma unroll 8
        for (int k = 0; k < HID; k++)
            s = fmaf(acc[n * HID + k], dw1[k * HID + j], s);
    }
    t1[q][j] = fmaxf(s, 0.f);
    __syncthreads();
    if (tid < 128) {
        int q2 = tid >> 5, j2 = tid & 31;
        int n2 = blockIdx.x * 4 + q2;
        if (n2 < Nn) {
            float o = db2[j2];
#pragma unroll 8
            for (int k = 0; k < HID; k++)
                o = fmaf(t1[q2][k], dw2[k * NHH + j2], o);
            meshh[n2 * NHH + j2] = o;
        }
    }
}

// ---------------- node decoder (ds) + Euler step + output --------------------
__global__ void dec_ds_kernel(const float* __restrict__ acc,
                              const float* __restrict__ dw1, const float* __restrict__ db1,
                              const float* __restrict__ dw2, const float* __restrict__ db2,
                              const float* __restrict__ Fprev_in,
                              const float* __restrict__ dtp,
                              float* __restrict__ Fprev_out,
                              float* __restrict__ outF, float* __restrict__ outFd,
                              int step, int nsteps, int Nn)
{
    __shared__ float t1[4][64];
    int tid = threadIdx.x;
    int q = tid >> 6, j = tid & 63;
    int n = blockIdx.x * 4 + q;
    float s = db1[j];
    if (n < Nn) {
#pragma unroll 8
        for (int k = 0; k < HID; k++)
            s = fmaf(acc[n * HID + k], dw1[k * HID + j], s);
    }
    t1[q][j] = fmaxf(s, 0.f);
    __syncthreads();
    if (tid < 8) {
        int q2 = tid >> 1, f = tid & 1;
        int n2 = blockIdx.x * 4 + q2;
        if (n2 < Nn) {
            float o = db2[f];
#pragma unroll 8
            for (int k = 0; k < HID; k++)
                o = fmaf(t1[q2][k], dw2[k * NFLD + f], o);
            float fp = Fprev_in[n2 * NFLD + f];
            float fc = fmaf(dtp[0], o, fp);
            outF [(n2 * nsteps + step) * NFLD + f] = fc;
            outFd[(n2 * nsteps + step) * NFLD + f] = o;
            Fprev_out[n2 * NFLD + f] = fc;
        }
    }
}

// ---------------- launch ------------------------------------------------------
extern "C" void kernel_launch(void* const* d_in, const int* in_sizes, int n_in,
                              void* d_out, int out_size)
{
    const float* F_initial     = (const float*)d_in[0];
    const float* mesh_features = (const float*)d_in[1];
    const int*   edge_index    = (const int*)  d_in[2];
    const float* F_boundary    = (const float*)d_in[3];
    const float* dtp           = (const float*)d_in[4];
    const float* md_w0  = (const float*)d_in[5];
    const float* md_b0  = (const float*)d_in[6];
    const float* md_wh  = (const float*)d_in[7];
    const float* md_bh  = (const float*)d_in[8];
    const float* md_dw1 = (const float*)d_in[9];
    const float* md_db1 = (const float*)d_in[10];
    const float* md_dw2 = (const float*)d_in[11];
    const float* md_db2 = (const float*)d_in[12];
    const float* ds_encw = (const float*)d_in[13];
    const float* ds_encb = (const float*)d_in[14];
    const float* ds_w0  = (const float*)d_in[15];
    const float* ds_b0  = (const float*)d_in[16];
    const float* ds_wh  = (const float*)d_in[17];
    const float* ds_bh  = (const float*)d_in[18];
    const float* ds_dw1 = (const float*)d_in[19];
    const float* ds_db1 = (const float*)d_in[20];
    const float* ds_dw2 = (const float*)d_in[21];
    const float* ds_db2 = (const float*)d_in[22];

    int Nn = in_sizes[0] / NFLD;
    int E  = in_sizes[2] / 2;

    float *Ptop, *Pbot, *acc, *meshh, *Fprev;
    cudaGetSymbolAddress((void**)&Ptop,  g_Ptop);
    cudaGetSymbolAddress((void**)&Pbot,  g_Pbot);
    cudaGetSymbolAddress((void**)&acc,   g_acc);
    cudaGetSymbolAddress((void**)&meshh, g_meshh);
    cudaGetSymbolAddress((void**)&Fprev, g_Fprev);

    const size_t SMEM = (size_t)(2 * 64 * 128 + 2 * 64 * 64) * sizeof(float);  // 98304
    cudaFuncSetAttribute(edge_mlp_kernel,
                         cudaFuncAttributeMaxDynamicSharedMemorySize, (int)SMEM);

    const int* srcp = edge_index;
    const int* dstp = edge_index + E;

    int nb_node = (Nn * HID + 255) / 256;
    int nb_dec  = (Nn + 3) / 4;
    int nsteps  = NTS - 1;
    int nb_edge = (E + 63) / 64;

    float* outF  = (float*)d_out;
    float* outFd = outF + (size_t)out_size / 2;

    // ---- mesh descriptor pass ----
    proj_md_kernel<<<nb_node, 256>>>(mesh_features, md_w0, Ptop, Pbot, acc, Nn);
    edge_mlp_kernel<<<nb_edge, 256, SMEM>>>(Ptop, Pbot, md_b0, md_wh, md_bh,
                                            srcp, dstp, acc, E);
    dec_md_kernel<<<nb_dec, 256>>>(acc, md_dw1, md_db1, md_dw2, md_db2, meshh, Nn);

    // ---- timesteps ----
    for (int t = 1; t < NTS; t++) {
        const float* fprev_in = (t == 1) ? F_initial : (const float*)Fprev;
        encproj_ds_kernel<<<nb_dec, 256>>>(meshh, fprev_in, F_boundary, t,
                                           ds_encw, ds_encb, ds_w0,
                                           Ptop, Pbot, acc, Nn);
        edge_mlp_kernel<<<nb_edge, 256, SMEM>>>(Ptop, Pbot, ds_b0, ds_wh, ds_bh,
                                                srcp, dstp, acc, E);
        dec_ds_kernel<<<nb_dec, 256>>>(acc, ds_dw1, ds_db1, ds_dw2, ds_db2,
                                       fprev_in, dtp, Fprev, outF, outFd,
                                       t - 1, nsteps, Nn);
    }
}

// round 9
// speedup vs baseline: 2.7002x; 2.7002x over previous
#include <cuda_runtime.h>
#include <cuda_bf16.h>
#include <cstdint>

#define HID   64
#define NFLD  2
#define NHH   32
#define NMF   8
#define NTS   4
#define NLAY  9
#define MAXN  10016

// ---------------- scratch (device globals; no allocation allowed) -----------
__device__ float g_Ptop[MAXN * HID];
__device__ float g_Pbot[MAXN * HID];
__device__ float g_acc [MAXN * HID];
__device__ float g_meshh[MAXN * NHH];
__device__ float g_Fprev[MAXN * NFLD];
// pre-converted edge weights: [set][layer][n][k] bf16 hi/lo, chunk-swizzled
__device__ __align__(16) __nv_bfloat16 g_WBhi[2][NLAY * HID * HID];
__device__ __align__(16) __nv_bfloat16 g_WBlo[2][NLAY * HID * HID];

// ---------------- helpers -----------------------------------------------------
__device__ __forceinline__ uint32_t s2u(const void* p) {
    uint32_t a;
    asm("{ .reg .u64 t; cvta.to.shared.u64 t, %1; cvt.u32.u64 %0, t; }"
        : "=r"(a) : "l"(p));
    return a;
}
__device__ __forceinline__ void ldsm4(uint32_t* r, uint32_t addr) {
    asm volatile("ldmatrix.sync.aligned.m8n8.x4.shared.b16 {%0,%1,%2,%3}, [%4];"
                 : "=r"(r[0]), "=r"(r[1]), "=r"(r[2]), "=r"(r[3]) : "r"(addr));
}
__device__ __forceinline__ void mma16816(float* c, const uint32_t* a, const uint32_t* b) {
    asm volatile("mma.sync.aligned.m16n8k16.row.col.f32.bf16.bf16.f32 "
                 "{%0,%1,%2,%3}, {%4,%5,%6,%7}, {%8,%9}, {%0,%1,%2,%3};"
                 : "+f"(c[0]), "+f"(c[1]), "+f"(c[2]), "+f"(c[3])
                 : "r"(a[0]), "r"(a[1]), "r"(a[2]), "r"(a[3]), "r"(b[0]), "r"(b[1]));
}
__device__ __forceinline__ uint32_t packbf(float x, float y) {
    __nv_bfloat16 hx = __float2bfloat16(x), hy = __float2bfloat16(y);
    return (uint32_t)__bfloat16_as_ushort(hx) | ((uint32_t)__bfloat16_as_ushort(hy) << 16);
}

// ---------------- weight pre-conversion (once per weight set) ----------------
// W[l][k][j] fp32 -> Wt[l][n=j][k] bf16 hi/lo, 16B-chunk XOR swizzle per row.
__global__ void prep_wb_kernel(const float* __restrict__ Wh,
                               __nv_bfloat16* __restrict__ hi,
                               __nv_bfloat16* __restrict__ lo)
{
    int idx = blockIdx.x * 256 + threadIdx.x;
    if (idx >= NLAY * HID * HID) return;
    int l = idx >> 12, r = idx & 4095;
    int j = r >> 6, k = r & 63;
    float w = Wh[l * 4096 + k * 64 + j];
    __nv_bfloat16 h = __float2bfloat16(w);
    __nv_bfloat16 lo_ = __float2bfloat16(w - __bfloat162float(h));
    int off = j * 128 + k * 2;
    int sw  = off ^ ((off >> 3) & 0x70);   // chunk16 ^= (j&7)
    hi[l * 4096 + (sw >> 1)] = h;
    lo[l * 4096 + (sw >> 1)] = lo_;
}

// ---------------- per-node projection (mesh descriptor) ----------------------
__global__ void proj_md_kernel(const float* __restrict__ X,
                               const float* __restrict__ W0,
                               float* __restrict__ Ptop, float* __restrict__ Pbot,
                               float* __restrict__ acc, int Nn)
{
    int idx = blockIdx.x * blockDim.x + threadIdx.x;
    if (idx >= Nn * HID) return;
    int n = idx >> 6, j = idx & 63;
    float st = 0.f, sb = 0.f;
#pragma unroll
    for (int k = 0; k < NMF; k++) {
        float x = X[n * NMF + k];
        st = fmaf(x, W0[k * HID + j], st);
        sb = fmaf(x, W0[(NMF + k) * HID + j], sb);
    }
    Ptop[idx] = st;
    Pbot[idx] = sb;
    acc[idx]  = 0.f;
}

// ---------------- fused node encoder + projection (ds) -----------------------
__global__ void encproj_ds_kernel(const float* __restrict__ meshh,
                                  const float* __restrict__ Fprev,
                                  const float* __restrict__ Fb, int t,
                                  const float* __restrict__ encW,
                                  const float* __restrict__ encb,
                                  const float* __restrict__ W0,
                                  float* __restrict__ Ptop, float* __restrict__ Pbot,
                                  float* __restrict__ acc, int Nn)
{
    __shared__ float sh[4][64];
    int tid = threadIdx.x;
    int q = tid >> 6, j = tid & 63;
    int n = blockIdx.x * 4 + q;
    float s = encb[j];
    if (n < Nn) {
#pragma unroll
        for (int k = 0; k < NHH; k++)
            s = fmaf(meshh[n * NHH + k], encW[k * HID + j], s);
        s = fmaf(Fprev[n * NFLD + 0], encW[(NHH + 0) * HID + j], s);
        s = fmaf(Fprev[n * NFLD + 1], encW[(NHH + 1) * HID + j], s);
        s = fmaf(Fb[n * NTS + t],     encW[(NHH + 2) * HID + j], s);
    }
    sh[q][j] = fmaxf(s, 0.f);
    __syncthreads();
    if (n < Nn) {
        float st = 0.f, sb = 0.f;
#pragma unroll 8
        for (int k = 0; k < HID; k++) {
            float x = sh[q][k];
            st = fmaf(x, W0[k * HID + j], st);
            sb = fmaf(x, W0[(HID + k) * HID + j], sb);
        }
        int idx = n * HID + j;
        Ptop[idx] = st;
        Pbot[idx] = sb;
        acc[idx]  = 0.f;
    }
}

// ---------------- HMMA edge MLP + scatter -------------------------------------
// Tile 128e x 64c, 256 threads (8 warps: 4 edge-blocks x 2 col-blocks).
// bf16x3 split: C = Ah@Wh + Al@Wh + Ah@Wl (fp32 accum in HMMA).
// A smem [e][k] bf16, row 128B, 16B-chunk XOR swizzle (chunk ^= e&7).
// Wt smem [n][k] bf16 likewise. ldmatrix non-trans matches both fragments.
// C stays in registers -> epilogue bias+relu+re-split directly; last layer
// scatters fp32 atomics. A and W double-buffered; one __syncthreads/layer.
#define SM_A0HI  0
#define SM_A0LO  16384
#define SM_A1HI  32768
#define SM_A1LO  49152
#define SM_W0HI  65536
#define SM_W0LO  73728
#define SM_W1HI  81920
#define SM_W1LO  90112
#define SM_BIAS  98304
#define SM_TOTAL (98304 + NLAY * HID * 4)   // 100608

__global__ void __launch_bounds__(256, 2)
edge_mlp_tc_kernel(const float* __restrict__ Ptop, const float* __restrict__ Pbot,
                   const float* __restrict__ b0,
                   const __nv_bfloat16* __restrict__ WBhi,
                   const __nv_bfloat16* __restrict__ WBlo,
                   const float* __restrict__ Bh,
                   const int* __restrict__ srcp, const int* __restrict__ dstp,
                   float* __restrict__ acc, int E)
{
    extern __shared__ __align__(1024) char sm[];
    const int tid = threadIdx.x, lane = tid & 31, wid = tid >> 5;
    const int eb = wid & 3, cb = wid >> 2;
    const int e0 = blockIdx.x * 128;

    // ---- gather h0 = relu(Ptop[dst]+Pbot[src]+b0), split -> A0 hi/lo ----
    for (int u = tid; u < 128 * 8; u += 256) {
        int e = u & 127, oct = u >> 7;
        int ge = e0 + e;
        float v[8];
        if (ge < E) {
            int d = dstp[ge], s = srcp[ge];
            float4 t0 = *(const float4*)(Ptop + d * HID + oct * 8);
            float4 t1 = *(const float4*)(Ptop + d * HID + oct * 8 + 4);
            float4 p0 = *(const float4*)(Pbot + s * HID + oct * 8);
            float4 p1 = *(const float4*)(Pbot + s * HID + oct * 8 + 4);
            float4 c0 = *(const float4*)(b0 + oct * 8);
            float4 c1 = *(const float4*)(b0 + oct * 8 + 4);
            v[0] = fmaxf(t0.x + p0.x + c0.x, 0.f);
            v[1] = fmaxf(t0.y + p0.y + c0.y, 0.f);
            v[2] = fmaxf(t0.z + p0.z + c0.z, 0.f);
            v[3] = fmaxf(t0.w + p0.w + c0.w, 0.f);
            v[4] = fmaxf(t1.x + p1.x + c1.x, 0.f);
            v[5] = fmaxf(t1.y + p1.y + c1.y, 0.f);
            v[6] = fmaxf(t1.z + p1.z + c1.z, 0.f);
            v[7] = fmaxf(t1.w + p1.w + c1.w, 0.f);
        } else {
#pragma unroll
            for (int i = 0; i < 8; i++) v[i] = 0.f;
        }
        uint32_t hw[4], lw[4];
#pragma unroll
        for (int i = 0; i < 4; i++) {
            float a = v[2 * i], b = v[2 * i + 1];
            __nv_bfloat16 ha = __float2bfloat16(a), hb = __float2bfloat16(b);
            hw[i] = (uint32_t)__bfloat16_as_ushort(ha) | ((uint32_t)__bfloat16_as_ushort(hb) << 16);
            lw[i] = packbf(a - __bfloat162float(ha), b - __bfloat162float(hb));
        }
        int sw = (oct ^ (e & 7)) * 16;
        *(uint4*)(sm + SM_A0HI + e * 128 + sw) = make_uint4(hw[0], hw[1], hw[2], hw[3]);
        *(uint4*)(sm + SM_A0LO + e * 128 + sw) = make_uint4(lw[0], lw[1], lw[2], lw[3]);
    }

    // ---- stage layer-0 weights + all biases ----
    for (int i = tid; i < 512; i += 256) {
        ((uint4*)(sm + SM_W0HI))[i] = ((const uint4*)WBhi)[i];
        ((uint4*)(sm + SM_W0LO))[i] = ((const uint4*)WBlo)[i];
    }
    for (int i = tid; i < NLAY * HID; i += 256)
        ((float*)(sm + SM_BIAS))[i] = Bh[i];
    __syncthreads();

    // per-thread ldmatrix row components
    const int rA  = lane & 15;                      // A row within m16
    const int khA = lane >> 4;                      // A k-half (0/1)
    const int eA0 = eb * 32 + rA;                   // mt=0 edge row
    const int nB0 = cb * 32 + (lane & 7) + ((lane >> 4) << 3);  // np=0 W row
    const int khB = (lane >> 3) & 1;                // W k-half

    int abuf = 0;
    for (int l = 0; l < NLAY; l++) {
        const uint32_t AhiB = s2u(sm + (abuf ? SM_A1HI : SM_A0HI));
        const uint32_t AloB = s2u(sm + (abuf ? SM_A1LO : SM_A0LO));
        const uint32_t WhiB = s2u(sm + ((l & 1) ? SM_W1HI : SM_W0HI));
        const uint32_t WloB = s2u(sm + ((l & 1) ? SM_W1LO : SM_W0LO));

        float C[2][4][4];
#pragma unroll
        for (int mt = 0; mt < 2; mt++)
#pragma unroll
            for (int nt = 0; nt < 4; nt++)
#pragma unroll
                for (int i = 0; i < 4; i++) C[mt][nt][i] = 0.f;

#pragma unroll
        for (int kt = 0; kt < 4; kt++) {
            uint32_t ah[2][4], al[2][4], bh[4][2], bl[4][2];
#pragma unroll
            for (int mt = 0; mt < 2; mt++) {
                int e = eA0 + mt * 16;
                uint32_t off = (uint32_t)(e * 128 + ((((kt << 1) + khA) ^ (e & 7)) << 4));
                ldsm4(ah[mt], AhiB + off);
                ldsm4(al[mt], AloB + off);
            }
#pragma unroll
            for (int np = 0; np < 2; np++) {
                int n = nB0 + np * 16;
                uint32_t off = (uint32_t)(n * 128 + ((((kt << 1) + khB) ^ (n & 7)) << 4));
                uint32_t t4[4];
                ldsm4(t4, WhiB + off);
                bh[np * 2][0] = t4[0]; bh[np * 2][1] = t4[1];
                bh[np * 2 + 1][0] = t4[2]; bh[np * 2 + 1][1] = t4[3];
                ldsm4(t4, WloB + off);
                bl[np * 2][0] = t4[0]; bl[np * 2][1] = t4[1];
                bl[np * 2 + 1][0] = t4[2]; bl[np * 2 + 1][1] = t4[3];
            }
#pragma unroll
            for (int mt = 0; mt < 2; mt++)
#pragma unroll
                for (int nt = 0; nt < 4; nt++) {
                    mma16816(C[mt][nt], ah[mt], bh[nt]);
                    mma16816(C[mt][nt], al[mt], bh[nt]);
                    mma16816(C[mt][nt], ah[mt], bl[nt]);
                }
        }

        // prefetch next layer's weights to registers (overlaps epilogue)
        uint4 wph[2], wpl[2];
        if (l + 1 < NLAY) {
            const uint4* gh = (const uint4*)(WBhi + (l + 1) * 4096);
            const uint4* gl = (const uint4*)(WBlo + (l + 1) * 4096);
            wph[0] = gh[tid * 2]; wph[1] = gh[tid * 2 + 1];
            wpl[0] = gl[tid * 2]; wpl[1] = gl[tid * 2 + 1];
        }

        const float* bsl = (const float*)(sm + SM_BIAS) + l * HID;

        if (l + 1 < NLAY) {
            char* dh = sm + (abuf ? SM_A0HI : SM_A1HI);
            char* dl = sm + (abuf ? SM_A0LO : SM_A1LO);
#pragma unroll
            for (int mt = 0; mt < 2; mt++) {
#pragma unroll
                for (int half = 0; half < 2; half++) {
                    int e = eb * 32 + mt * 16 + (lane >> 2) + half * 8;
#pragma unroll
                    for (int nt = 0; nt < 4; nt++) {
                        int n = cb * 32 + nt * 8 + (lane & 3) * 2;
                        float v0 = fmaxf(C[mt][nt][half * 2 + 0] + bsl[n], 0.f);
                        float v1 = fmaxf(C[mt][nt][half * 2 + 1] + bsl[n + 1], 0.f);
                        __nv_bfloat16 h0 = __float2bfloat16(v0);
                        __nv_bfloat16 h1 = __float2bfloat16(v1);
                        uint32_t hp = (uint32_t)__bfloat16_as_ushort(h0) |
                                      ((uint32_t)__bfloat16_as_ushort(h1) << 16);
                        uint32_t lp = packbf(v0 - __bfloat162float(h0),
                                             v1 - __bfloat162float(h1));
                        uint32_t off = (uint32_t)(e * 128 +
                                       ((((cb << 2) + nt) ^ (e & 7)) << 4) + ((lane & 3) << 2));
                        *(uint32_t*)(dh + off) = hp;
                        *(uint32_t*)(dl + off) = lp;
                    }
                }
            }
        } else {
            // last layer: fp32 atomic scatter by src
#pragma unroll
            for (int mt = 0; mt < 2; mt++) {
#pragma unroll
                for (int half = 0; half < 2; half++) {
                    int e  = eb * 32 + mt * 16 + (lane >> 2) + half * 8;
                    int ge = e0 + e;
                    if (ge < E) {
                        int node = srcp[ge];
                        float* ap = acc + node * HID;
#pragma unroll
                        for (int nt = 0; nt < 4; nt++) {
                            int n = cb * 32 + nt * 8 + (lane & 3) * 2;
                            atomicAdd(ap + n,     C[mt][nt][half * 2 + 0] + bsl[n]);
                            atomicAdd(ap + n + 1, C[mt][nt][half * 2 + 1] + bsl[n + 1]);
                        }
                    }
                }
            }
        }

        if (l + 1 < NLAY) {
            char* wdh = sm + ((l & 1) ? SM_W0HI : SM_W1HI);
            char* wdl = sm + ((l & 1) ? SM_W0LO : SM_W1LO);
            ((uint4*)wdh)[tid * 2] = wph[0]; ((uint4*)wdh)[tid * 2 + 1] = wph[1];
            ((uint4*)wdl)[tid * 2] = wpl[0]; ((uint4*)wdl)[tid * 2 + 1] = wpl[1];
        }
        __syncthreads();
        abuf ^= 1;
    }
}

// ---------------- node decoder (mesh descriptor) -----------------------------
__global__ void dec_md_kernel(const float* __restrict__ acc,
                              const float* __restrict__ dw1, const float* __restrict__ db1,
                              const float* __restrict__ dw2, const float* __restrict__ db2,
                              float* __restrict__ meshh, int Nn)
{
    __shared__ float t1[4][64];
    int tid = threadIdx.x;
    int q = tid >> 6, j = tid & 63;
    int n = blockIdx.x * 4 + q;
    float s = db1[j];
    if (n < Nn) {
#pragma unroll 8
        for (int k = 0; k < HID; k++)
            s = fmaf(acc[n * HID + k], dw1[k * HID + j], s);
    }
    t1[q][j] = fmaxf(s, 0.f);
    __syncthreads();
    if (tid < 128) {
        int q2 = tid >> 5, j2 = tid & 31;
        int n2 = blockIdx.x * 4 + q2;
        if (n2 < Nn) {
            float o = db2[j2];
#pragma unroll 8
            for (int k = 0; k < HID; k++)
                o = fmaf(t1[q2][k], dw2[k * NHH + j2], o);
            meshh[n2 * NHH + j2] = o;
        }
    }
}

// ---------------- node decoder (ds) + Euler step + output --------------------
__global__ void dec_ds_kernel(const float* __restrict__ acc,
                              const float* __restrict__ dw1, const float* __restrict__ db1,
                              const float* __restrict__ dw2, const float* __restrict__ db2,
                              const float* __restrict__ Fprev_in,
                              const float* __restrict__ dtp,
                              float* __restrict__ Fprev_out,
                              float* __restrict__ outF, float* __restrict__ outFd,
                              int step, int nsteps, int Nn)
{
    __shared__ float t1[4][64];
    int tid = threadIdx.x;
    int q = tid >> 6, j = tid & 63;
    int n = blockIdx.x * 4 + q;
    float s = db1[j];
    if (n < Nn) {
#pragma unroll 8
        for (int k = 0; k < HID; k++)
            s = fmaf(acc[n * HID + k], dw1[k * HID + j], s);
    }
    t1[q][j] = fmaxf(s, 0.f);
    __syncthreads();
    if (tid < 8) {
        int q2 = tid >> 1, f = tid & 1;
        int n2 = blockIdx.x * 4 + q2;
        if (n2 < Nn) {
            float o = db2[f];
#pragma unroll 8
            for (int k = 0; k < HID; k++)
                o = fmaf(t1[q2][k], dw2[k * NFLD + f], o);
            float fp = Fprev_in[n2 * NFLD + f];
            float fc = fmaf(dtp[0], o, fp);
            outF [(n2 * nsteps + step) * NFLD + f] = fc;
            outFd[(n2 * nsteps + step) * NFLD + f] = o;
            Fprev_out[n2 * NFLD + f] = fc;
        }
    }
}

// ---------------- launch ------------------------------------------------------
extern "C" void kernel_launch(void* const* d_in, const int* in_sizes, int n_in,
                              void* d_out, int out_size)
{
    const float* F_initial     = (const float*)d_in[0];
    const float* mesh_features = (const float*)d_in[1];
    const int*   edge_index    = (const int*)  d_in[2];
    const float* F_boundary    = (const float*)d_in[3];
    const float* dtp           = (const float*)d_in[4];
    const float* md_w0  = (const float*)d_in[5];
    const float* md_b0  = (const float*)d_in[6];
    const float* md_wh  = (const float*)d_in[7];
    const float* md_bh  = (const float*)d_in[8];
    const float* md_dw1 = (const float*)d_in[9];
    const float* md_db1 = (const float*)d_in[10];
    const float* md_dw2 = (const float*)d_in[11];
    const float* md_db2 = (const float*)d_in[12];
    const float* ds_encw = (const float*)d_in[13];
    const float* ds_encb = (const float*)d_in[14];
    const float* ds_w0  = (const float*)d_in[15];
    const float* ds_b0  = (const float*)d_in[16];
    const float* ds_wh  = (const float*)d_in[17];
    const float* ds_bh  = (const float*)d_in[18];
    const float* ds_dw1 = (const float*)d_in[19];
    const float* ds_db1 = (const float*)d_in[20];
    const float* ds_dw2 = (const float*)d_in[21];
    const float* ds_db2 = (const float*)d_in[22];

    int Nn = in_sizes[0] / NFLD;
    int E  = in_sizes[2] / 2;

    float *Ptop, *Pbot, *acc, *meshh, *Fprev;
    __nv_bfloat16 *wbhi, *wblo;
    cudaGetSymbolAddress((void**)&Ptop,  g_Ptop);
    cudaGetSymbolAddress((void**)&Pbot,  g_Pbot);
    cudaGetSymbolAddress((void**)&acc,   g_acc);
    cudaGetSymbolAddress((void**)&meshh, g_meshh);
    cudaGetSymbolAddress((void**)&Fprev, g_Fprev);
    cudaGetSymbolAddress((void**)&wbhi,  g_WBhi);
    cudaGetSymbolAddress((void**)&wblo,  g_WBlo);

    cudaFuncSetAttribute(edge_mlp_tc_kernel,
                         cudaFuncAttributeMaxDynamicSharedMemorySize, SM_TOTAL);

    const int* srcp = edge_index;
    const int* dstp = edge_index + E;

    int nb_node = (Nn * HID + 255) / 256;
    int nb_dec  = (Nn + 3) / 4;
    int nsteps  = NTS - 1;
    int nb_edge = (E + 127) / 128;
    int nb_prep = (NLAY * HID * HID + 255) / 256;

    float* outF  = (float*)d_out;
    float* outFd = outF + (size_t)out_size / 2;

    __nv_bfloat16* wbhi_md = wbhi;
    __nv_bfloat16* wblo_md = wblo;
    __nv_bfloat16* wbhi_ds = wbhi + NLAY * HID * HID;
    __nv_bfloat16* wblo_ds = wblo + NLAY * HID * HID;

    // ---- weight pre-conversion (both sets) ----
    prep_wb_kernel<<<nb_prep, 256>>>(md_wh, wbhi_md, wblo_md);
    prep_wb_kernel<<<nb_prep, 256>>>(ds_wh, wbhi_ds, wblo_ds);

    // ---- mesh descriptor pass ----
    proj_md_kernel<<<nb_node, 256>>>(mesh_features, md_w0, Ptop, Pbot, acc, Nn);
    edge_mlp_tc_kernel<<<nb_edge, 256, SM_TOTAL>>>(Ptop, Pbot, md_b0,
                                                   wbhi_md, wblo_md, md_bh,
                                                   srcp, dstp, acc, E);
    dec_md_kernel<<<nb_dec, 256>>>(acc, md_dw1, md_db1, md_dw2, md_db2, meshh, Nn);

    // ---- timesteps ----
    for (int t = 1; t < NTS; t++) {
        const float* fprev_in = (t == 1) ? F_initial : (const float*)Fprev;
        encproj_ds_kernel<<<nb_dec, 256>>>(meshh, fprev_in, F_boundary, t,
                                           ds_encw, ds_encb, ds_w0,
                                           Ptop, Pbot, acc, Nn);
        edge_mlp_tc_kernel<<<nb_edge, 256, SM_TOTAL>>>(Ptop, Pbot, ds_b0,
                                                       wbhi_ds, wblo_ds, ds_bh,
                                                       srcp, dstp, acc, E);
        dec_ds_kernel<<<nb_dec, 256>>>(acc, ds_dw1, ds_db1, ds_dw2, ds_db2,
                                       fprev_in, dtp, Fprev, outF, outFd,
                                       t - 1, nsteps, Nn);
    }
}